// round 5
// baseline (speedup 1.0000x reference)
#include <cuda_runtime.h>

// Problem constants
#define BB   2048
#define DD   256
#define OUTN 256
#define KK   16
#define DKN  (DD * KK)   // 4096

// Main-kernel tiling
#define BTILE   32
#define OTILE   32
#define NTHR    256
#define DCHUNK  8                            // d-slices per pipeline stage
#define NCHUNK  (DD / DCHUNK)                // 32
#define CHUNK_FLOATS (DCHUNK * KK * OTILE)   // 4096 floats = 16KB
#define LWB     (BTILE * DCHUNK)             // 256 floats per lw buffer: [bi][dd]
#define NLWBUF  4
#define SMEM_BYTES ((2 * CHUNK_FLOATS + NLWBUF * LWB) * 4)   // 36,864 B

// Scratch (device global; no allocation allowed)
__device__ float g_Vt[DKN * OUTN];    // [d][k][out] = values^T + g_k * skip_w^T  (4 MB)

__constant__ float c_grid[16] = {
    -1.0f,         -0.86666667f, -0.73333333f, -0.6f,
    -0.46666667f,  -0.33333334f, -0.2f,        -0.06666667f,
     0.06666667f,   0.2f,         0.33333333f,  0.46666667f,
     0.6f,          0.73333333f,  0.86666667f,  1.0f
};

// ---------------------------------------------------------------------------
// Kernel 1: build Vt[d][k][out] = values[out][d][k] + grid[k] * skip_w[out][d]
// (hat-basis interpolation of a linear function on its own grid is exact, so
//  the skip connection folds into the table)
// ---------------------------------------------------------------------------
__global__ void k_build_vt(const float* __restrict__ vals,
                           const float* __restrict__ sw) {
    __shared__ float tile[32][33];
    __shared__ float s_sw[2][32];    // 32 dk span exactly 2 d
    int tx = threadIdx.x, ty = threadIdx.y;
    int dkbase = blockIdx.x * 32;
    int obase  = blockIdx.y * 32;
    int d0 = dkbase >> 4;

    if (ty < 2)
        s_sw[ty][tx] = sw[(obase + tx) * DD + d0 + ty];
#pragma unroll
    for (int i = 0; i < 32; i += 8)
        tile[ty + i][tx] = vals[(obase + ty + i) * DKN + dkbase + tx];
    __syncthreads();
#pragma unroll
    for (int i = 0; i < 32; i += 8) {
        int dk = dkbase + ty + i;
        int k  = dk & 15;
        int dl = (dk >> 4) - d0;
        g_Vt[dk * OUTN + obase + tx] = tile[tx][ty + i] + c_grid[k] * s_sw[dl][tx];
    }
}

// ---------------------------------------------------------------------------
// Kernel 2: smem-staged spline gather.
// Block: 256 threads, BTILE=32 b x OTILE=32 outs; 32 chunks of 8 d's.
//   og = tid & 7  -> outs [o0+4og .. +3] (float4);  bg = tid >> 3 -> b-row.
// Table slices cp.async'd into a 2-stage ring; (l+w) computed on the fly into
// a 4-deep ring laid out [bi][dd] so 4 d's load as one LDS.128.
// Gathers conflict-free: each quarter-warp phase (8 og lanes, one bg) reads
// one contiguous 128B table row.
// ---------------------------------------------------------------------------
__device__ __forceinline__ void cp_chunk(float* s_tab, int c, int o0, int tid) {
    float* dstbase = s_tab + (c & 1) * CHUNK_FLOATS;
    int d0k = c * DCHUNK;
#pragma unroll
    for (int r = 0; r < 4; ++r) {
        int lin  = (r * NTHR + tid) * 4;          // float offset in chunk
        int doff = lin >> 9;                      // 512 floats per d-slice
        int win  = lin & 511;
        int k    = win >> 5;
        int j    = win & 31;
        const float* src = g_Vt + (((d0k + doff) * KK + k) << 8) + o0 + j;
        unsigned saddr = (unsigned)__cvta_generic_to_shared(dstbase + lin);
        asm volatile("cp.async.cg.shared.global [%0], [%1], 16;\n"
                     :: "r"(saddr), "l"(src) : "memory");
    }
}

// Bucketize x for chunk c: thread (dd = tid&7, bi = tid>>3) handles one (b,d).
// Layout: s_lw[buf][bi*8 + dd] -> lanes write 32 consecutive banks, no conflict.
__device__ __forceinline__ void compute_lw(float* s_lw, const float* __restrict__ x,
                                           int b0, int c, int tid) {
    int dd = tid & 7;
    int bi = tid >> 3;
    float xv = x[(b0 + bi) * DD + c * DCHUNK + dd];
    float xc = fminf(fmaxf(xv, -1.0f), 1.0f);
    float t = (xc + 1.0f) * 7.5f;
    int j = (int)t;
    if (j > 14) j = 14;
    if (j > 0 && xc <= c_grid[j]) {
        --j;
    } else if (j < 14 && xc > c_grid[j + 1]) {
        ++j;
    }
    float w = (xc - c_grid[j]) / (c_grid[j + 1] - c_grid[j]);
    w = fminf(fmaxf(w, 0.0f), 1.0f);
    s_lw[(c & (NLWBUF - 1)) * LWB + bi * DCHUNK + dd] =
        fminf((float)j + w, 14.999999f);
}

__global__ __launch_bounds__(NTHR, 5) void k_main(const float* __restrict__ x,
                                                  const float* __restrict__ skip_b,
                                                  float* __restrict__ y) {
    extern __shared__ float smem[];
    float* s_tab = smem;                         // [2][8][16][32]
    float* s_lw  = smem + 2 * CHUNK_FLOATS;      // [4][32][8]

    const int tid = threadIdx.x;
    const int b0 = (blockIdx.x >> 3) * BTILE;
    const int o0 = (blockIdx.x & 7) * OTILE;

    // ---- Prologue ----
    cp_chunk(s_tab, 0, o0, tid);
    asm volatile("cp.async.commit_group;\n" ::: "memory");
    compute_lw(s_lw, x, b0, 0, tid);
    compute_lw(s_lw, x, b0, 1, tid);

    const int og = tid & 7;
    const int bg = tid >> 3;
    // split accumulators: 8 independent 1-FMA-deep chains
    float4 acc1 = make_float4(0.f, 0.f, 0.f, 0.f);
    float4 acc2 = acc1;

#pragma unroll 1
    for (int c = 0; c < NCHUNK; ++c) {
        asm volatile("cp.async.wait_group 0;\n" ::: "memory");
        __syncthreads();   // tab[c] + lw[c] visible; tab[(c+1)&1] & lw[(c+2)&3] free

        if (c + 1 < NCHUNK) {
            cp_chunk(s_tab, c + 1, o0, tid);
            asm volatile("cp.async.commit_group;\n" ::: "memory");
        }
        if (c + 2 < NCHUNK)
            compute_lw(s_lw, x, b0, c + 2, tid);

        const float* tb = s_tab + (c & 1) * CHUNK_FLOATS;
        const float4* lwv = (const float4*)(s_lw + (c & (NLWBUF - 1)) * LWB + bg * DCHUNK);

#pragma unroll
        for (int q = 0; q < DCHUNK / 4; ++q) {      // 2 quads of d
            float4 lw4 = lwv[q];
            const float wq[4] = { lw4.x, lw4.y, lw4.z, lw4.w };
#pragma unroll
            for (int h = 0; h < 2; ++h) {           // 2 pairs per quad
                float4 vl[2], vr[2];
                float  w[2];
#pragma unroll
                for (int j2 = 0; j2 < 2; ++j2) {
                    int dd = q * 4 + h * 2 + j2;
                    float val = wq[h * 2 + j2];
                    float fl = floorf(val);
                    int l = (int)fl;
                    w[j2] = val - fl;
                    const float4* p =
                        (const float4*)(tb + dd * (KK * OTILE) + l * OTILE) + og;
                    vl[j2] = p[0];
                    vr[j2] = p[OTILE / 4];
                }
#pragma unroll
                for (int j2 = 0; j2 < 2; ++j2) {
                    float f0 = 1.0f - w[j2];
                    acc1.x = fmaf(f0, vl[j2].x, acc1.x);
                    acc1.y = fmaf(f0, vl[j2].y, acc1.y);
                    acc1.z = fmaf(f0, vl[j2].z, acc1.z);
                    acc1.w = fmaf(f0, vl[j2].w, acc1.w);
                    acc2.x = fmaf(w[j2], vr[j2].x, acc2.x);
                    acc2.y = fmaf(w[j2], vr[j2].y, acc2.y);
                    acc2.z = fmaf(w[j2], vr[j2].z, acc2.z);
                    acc2.w = fmaf(w[j2], vr[j2].w, acc2.w);
                }
            }
        }
    }

    // ---- Epilogue: combine chains, add bias, store ----
    float4 sb = *(const float4*)(skip_b + o0 + og * 4);
    float4 r = make_float4(acc1.x + acc2.x + sb.x,
                           acc1.y + acc2.y + sb.y,
                           acc1.z + acc2.z + sb.z,
                           acc1.w + acc2.w + sb.w);
    *(float4*)(y + (b0 + bg) * OUTN + o0 + og * 4) = r;
}

// ---------------------------------------------------------------------------
extern "C" void kernel_launch(void* const* d_in, const int* in_sizes, int n_in,
                              void* d_out, int out_size) {
    const float* x      = (const float*)d_in[0];  // (B, D)
    const float* values = (const float*)d_in[1];  // (OUT, D, K)
    const float* skip_w = (const float*)d_in[2];  // (OUT, D)
    const float* skip_b = (const float*)d_in[3];  // (OUT,)
    float* y = (float*)d_out;                     // (B, OUT)

    cudaFuncSetAttribute(k_main, cudaFuncAttributeMaxDynamicSharedMemorySize,
                         SMEM_BYTES);

    k_build_vt<<<dim3(DKN / 32, OUTN / 32), dim3(32, 8)>>>(values, skip_w);
    k_main<<<(BB / BTILE) * (OUTN / OTILE), NTHR, SMEM_BYTES>>>(x, skip_b, y);
}

// round 6
// speedup vs baseline: 1.0456x; 1.0456x over previous
#include <cuda_runtime.h>
#include <cuda_fp16.h>
#include <cstdint>

// Problem constants
#define BB   2048
#define DD   256
#define OUTN 256
#define KK   16
#define DKN  (DD * KK)   // 4096

// Main-kernel tiling
#define BTILE   32
#define OTILE   32
#define NTHR    256
#define DCHUNK  8                            // d-slices per pipeline stage
#define NCHUNK  (DD / DCHUNK)                // 32
#define CHUNK_HALFS (DCHUNK * KK * OTILE)    // 4096 halfs = 8KB
#define CHUNK_BYTES (CHUNK_HALFS * 2)        // 8192
#define OT_SLICE (DD * KK * OTILE)           // halfs per o-tile = 131072
#define LWB     (BTILE * DCHUNK)             // float2 per lw buffer: [bi][dd]
#define NLWBUF  4
// smem: tab 2x8KB @0, lw ring 4x2KB @16384, mbars @24576
#define SMEM_TAB_OFF  0
#define SMEM_LW_OFF   (2 * CHUNK_BYTES)                  // 16384
#define SMEM_MBAR_OFF (SMEM_LW_OFF + NLWBUF * LWB * 8)   // 24576
#define SMEM_BYTES    (SMEM_MBAR_OFF + 32)

// Scratch (device global; no allocation allowed)
// Layout: [ot][d][k][oi] halfs, ot = out>>5, oi = out&31.
__device__ __half g_Vt[8 * OT_SLICE];   // 2 MB

__constant__ float c_grid[16] = {
    -1.0f,         -0.86666667f, -0.73333333f, -0.6f,
    -0.46666667f,  -0.33333334f, -0.2f,        -0.06666667f,
     0.06666667f,   0.2f,         0.33333333f,  0.46666667f,
     0.6f,          0.73333333f,  0.86666667f,  1.0f
};

// ---------------------------------------------------------------------------
// mbarrier helpers
// ---------------------------------------------------------------------------
#define MBAR_INIT(addr, cnt) \
    asm volatile("mbarrier.init.shared.b64 [%0], %1;" :: "r"(addr), "r"(cnt) : "memory")
#define MBAR_EXPECT_TX(addr, bytes) \
    asm volatile("mbarrier.arrive.expect_tx.shared.b64 _, [%0], %1;" :: "r"(addr), "r"(bytes) : "memory")

__device__ __forceinline__ void mbar_wait_parity(uint32_t mbar, uint32_t parity) {
    uint32_t done;
    asm volatile(
        "{\n\t.reg .pred p;\n\t"
        "mbarrier.try_wait.parity.acquire.cta.shared::cta.b64 p, [%1], %2;\n\t"
        "selp.b32 %0, 1, 0, p;\n\t}"
        : "=r"(done) : "r"(mbar), "r"(parity) : "memory");
    if (!done) {
        asm volatile(
            "{\n\t.reg .pred P1;\n\t"
            "WAIT_LOOP_%=:\n\t"
            "mbarrier.try_wait.parity.acquire.cta.shared::cta.b64 P1, [%0], %1, 0x989680;\n\t"
            "@P1 bra.uni WAIT_DONE_%=;\n\t"
            "bra.uni WAIT_LOOP_%=;\n\t"
            "WAIT_DONE_%=:\n\t}"
            :: "r"(mbar), "r"(parity) : "memory");
    }
}

// ---------------------------------------------------------------------------
// Kernel 1: build g_Vt[ot][d][k][oi] = half(values[out][d][k] + grid[k]*skip_w[out][d])
// (hat-basis interpolation of a linear function on its own grid is exact, so
//  the skip connection folds into the table)
// ---------------------------------------------------------------------------
__global__ void k_build_vt(const float* __restrict__ vals,
                           const float* __restrict__ sw) {
    __shared__ float tile[32][33];
    __shared__ float s_sw[2][32];    // 32 dk span exactly 2 d
    int tx = threadIdx.x, ty = threadIdx.y;
    int dkbase = blockIdx.x * 32;
    int obase  = blockIdx.y * 32;
    int d0 = dkbase >> 4;
    int ot = obase >> 5;

    if (ty < 2)
        s_sw[ty][tx] = sw[(obase + tx) * DD + d0 + ty];
#pragma unroll
    for (int i = 0; i < 32; i += 8)
        tile[ty + i][tx] = vals[(obase + ty + i) * DKN + dkbase + tx];
    __syncthreads();
#pragma unroll
    for (int i = 0; i < 32; i += 8) {
        int dk = dkbase + ty + i;
        int k  = dk & 15;
        int d  = dk >> 4;
        int dl = d - d0;
        float v = tile[tx][ty + i] + c_grid[k] * s_sw[dl][tx];
        g_Vt[((ot * DD + d) * KK + k) * OTILE + tx] = __float2half_rn(v);
    }
}

// ---------------------------------------------------------------------------
// Kernel 2: smem-staged spline gather, fp16 table, bulk-copy staging.
// Block: 256 threads, BTILE=32 b x OTILE=32 outs; 32 chunks of 8 d's.
//   og = tid & 7  -> outs [o0+4og .. +3];  bg = tid >> 3 -> b-row.
// Each chunk's contiguous 8KB table slice lands via ONE cp.async.bulk into a
// 2-stage ring (mbarrier completion). (w, byte-offset) pairs precomputed into
// a 4-deep float2 ring. One barrier per chunk.
// ---------------------------------------------------------------------------

// Bucketize x for chunk c: thread (dd = tid&7, bi = tid>>3) handles one (b,d).
__device__ __forceinline__ void compute_lw(float2* s_lw, const float* __restrict__ x,
                                           int b0, int c, int tid) {
    int dd = tid & 7;
    int bi = tid >> 3;
    float xv = x[(b0 + bi) * DD + c * DCHUNK + dd];
    float xc = fminf(fmaxf(xv, -1.0f), 1.0f);
    float t = (xc + 1.0f) * 7.5f;
    int j = (int)t;
    if (j > 14) j = 14;
    if (j > 0 && xc <= c_grid[j]) {
        --j;
    } else if (j < 14 && xc > c_grid[j + 1]) {
        ++j;
    }
    float w = (xc - c_grid[j]) / (c_grid[j + 1] - c_grid[j]);
    w = fminf(fmaxf(w, 0.0f), 1.0f);
    float2 p;
    p.x = w;
    p.y = __int_as_float(j * (OTILE * 2));   // byte offset of k-row l within d-slice
    s_lw[(c & (NLWBUF - 1)) * LWB + bi * DCHUNK + dd] = p;
}

__global__ __launch_bounds__(NTHR, 6) void k_main(const float* __restrict__ x,
                                                  const float* __restrict__ skip_b,
                                                  float* __restrict__ y) {
    extern __shared__ char smem[];
    char*   s_tab = smem + SMEM_TAB_OFF;                  // [2][8KB]
    float2* s_lw  = (float2*)(smem + SMEM_LW_OFF);        // [4][32][8]
    uint32_t smem_base;
    asm("{ .reg .u64 t; cvta.to.shared.u64 t, %1; cvt.u32.u64 %0, t; }"
        : "=r"(smem_base) : "l"(smem));
    uint32_t mbar0 = smem_base + SMEM_MBAR_OFF;
    uint32_t mbar1 = mbar0 + 8;

    const int tid = threadIdx.x;
    const int b0 = (blockIdx.x >> 3) * BTILE;
    const int ot = blockIdx.x & 7;
    const int o0 = ot * OTILE;
    const __half* gsrc = g_Vt + ot * OT_SLICE;

    if (tid == 0) {
        MBAR_INIT(mbar0, 1);
        MBAR_INIT(mbar1, 1);
    }
    __syncthreads();

    // ---- Prologue: bulk-load chunk 0; bucketize chunks 0,1 ----
    if (tid == 0) {
        MBAR_EXPECT_TX(mbar0, CHUNK_BYTES);
        asm volatile(
            "cp.async.bulk.shared::cluster.global.mbarrier::complete_tx::bytes "
            "[%0], [%1], %2, [%3];"
            :: "r"(smem_base + SMEM_TAB_OFF), "l"(gsrc),
               "r"(CHUNK_BYTES), "r"(mbar0) : "memory");
    }
    compute_lw(s_lw, x, b0, 0, tid);
    compute_lw(s_lw, x, b0, 1, tid);

    const int og = tid & 7;
    const int bg = tid >> 3;
    float4 acc1 = make_float4(0.f, 0.f, 0.f, 0.f);
    float4 acc2 = acc1;

#pragma unroll 1
    for (int c = 0; c < NCHUNK; ++c) {
        __syncthreads();   // all warps done with buf (c+1)&1 (chunk c-1) & lw slots

        if (tid == 0 && c + 1 < NCHUNK) {
            uint32_t mb = ((c + 1) & 1) ? mbar1 : mbar0;
            MBAR_EXPECT_TX(mb, CHUNK_BYTES);
            asm volatile(
                "cp.async.bulk.shared::cluster.global.mbarrier::complete_tx::bytes "
                "[%0], [%1], %2, [%3];"
                :: "r"(smem_base + SMEM_TAB_OFF + ((c + 1) & 1) * CHUNK_BYTES),
                   "l"(gsrc + (c + 1) * CHUNK_HALFS),
                   "r"(CHUNK_BYTES), "r"(mb) : "memory");
        }
        if (c + 2 < NCHUNK)
            compute_lw(s_lw, x, b0, c + 2, tid);

        mbar_wait_parity((c & 1) ? mbar1 : mbar0, (c >> 1) & 1);

        const char* tb = s_tab + (c & 1) * CHUNK_BYTES + og * 8;
        const float4* lwv =
            (const float4*)(s_lw + (c & (NLWBUF - 1)) * LWB + bg * DCHUNK);

#pragma unroll
        for (int q = 0; q < DCHUNK / 2; ++q) {      // 2 d's per float4
            float4 lw2 = lwv[q];
#pragma unroll
            for (int h = 0; h < 2; ++h) {
                int dd = q * 2 + h;
                float w   = (h == 0) ? lw2.x : lw2.z;
                int   off = __float_as_int((h == 0) ? lw2.y : lw2.w);
                const char* p = tb + dd * (KK * OTILE * 2) + off;
                uint2 ul = *(const uint2*)(p);                    // vl: 4 halfs
                uint2 ur = *(const uint2*)(p + OTILE * 2);        // vr: next k row
                float2 vl0 = __half22float2(*(const __half2*)&ul.x);
                float2 vl1 = __half22float2(*(const __half2*)&ul.y);
                float2 vr0 = __half22float2(*(const __half2*)&ur.x);
                float2 vr1 = __half22float2(*(const __half2*)&ur.y);
                float f0 = 1.0f - w;
                acc1.x = fmaf(f0, vl0.x, acc1.x);
                acc1.y = fmaf(f0, vl0.y, acc1.y);
                acc1.z = fmaf(f0, vl1.x, acc1.z);
                acc1.w = fmaf(f0, vl1.y, acc1.w);
                acc2.x = fmaf(w, vr0.x, acc2.x);
                acc2.y = fmaf(w, vr0.y, acc2.y);
                acc2.z = fmaf(w, vr1.x, acc2.z);
                acc2.w = fmaf(w, vr1.y, acc2.w);
            }
        }
    }

    // ---- Epilogue: combine chains, add bias, store ----
    float4 sb = *(const float4*)(skip_b + o0 + og * 4);
    float4 r = make_float4(acc1.x + acc2.x + sb.x,
                           acc1.y + acc2.y + sb.y,
                           acc1.z + acc2.z + sb.z,
                           acc1.w + acc2.w + sb.w);
    *(float4*)(y + (b0 + bg) * OUTN + o0 + og * 4) = r;
}

// ---------------------------------------------------------------------------
extern "C" void kernel_launch(void* const* d_in, const int* in_sizes, int n_in,
                              void* d_out, int out_size) {
    const float* x      = (const float*)d_in[0];  // (B, D)
    const float* values = (const float*)d_in[1];  // (OUT, D, K)
    const float* skip_w = (const float*)d_in[2];  // (OUT, D)
    const float* skip_b = (const float*)d_in[3];  // (OUT,)
    float* y = (float*)d_out;                     // (B, OUT)

    cudaFuncSetAttribute(k_main, cudaFuncAttributeMaxDynamicSharedMemorySize,
                         SMEM_BYTES);

    k_build_vt<<<dim3(DKN / 32, OUTN / 32), dim3(32, 8)>>>(values, skip_w);
    k_main<<<(BB / BTILE) * (OUTN / OTILE), NTHR, SMEM_BYTES>>>(x, skip_b, y);
}

// round 8
// speedup vs baseline: 1.7563x; 1.6798x over previous
#include <cuda_runtime.h>
#include <cuda_fp16.h>
#include <cstdint>

// Problem constants
#define BB   2048
#define DD   256
#define OUTN 256
#define KK   16
#define DKN  (DD * KK)   // 4096 = GEMM K

// GEMM tiling
#define MT      64                 // CTA M tile
#define NT      64                 // CTA N tile
#define KC      64                 // halfs per K chunk (=128B rows)
#define NKCH    (DKN / KC)         // 64 chunks
#define STAGES  3
#define ASTG    8192               // 64 rows x 128B
#define BSTG    8192
#define STG_BYTES (ASTG + BSTG)    // 16KB / stage
#define SMEM_BYTES (STAGES * STG_BYTES)   // 48KB

// Scratch (device globals; no allocation allowed)
__device__ __half g_Phi[BB * DKN];   // [b][dk] fp16, 16 MB
__device__ __half g_V[OUTN * DKN];   // [o][dk] fp16,  2 MB

__constant__ float c_grid[16] = {
    -1.0f,         -0.86666667f, -0.73333333f, -0.6f,
    -0.46666667f,  -0.33333334f, -0.2f,        -0.06666667f,
     0.06666667f,   0.2f,         0.33333333f,  0.46666667f,
     0.6f,          0.73333333f,  0.86666667f,  1.0f
};

// ---------------------------------------------------------------------------
// Bucketize (validated semantics R1-R6)
// ---------------------------------------------------------------------------
__device__ __forceinline__ void bucketize(float xv, int& l, float& w) {
    float xc = fminf(fmaxf(xv, -1.0f), 1.0f);
    float t = (xc + 1.0f) * 7.5f;
    int j = (int)t;
    if (j > 14) j = 14;
    if (j > 0 && xc <= c_grid[j]) {
        --j;
    } else if (j < 14 && xc > c_grid[j + 1]) {
        ++j;
    }
    float ww = (xc - c_grid[j]) / (c_grid[j + 1] - c_grid[j]);
    w = fminf(fmaxf(ww, 0.0f), 1.0f);
    l = j;
}

// ---------------------------------------------------------------------------
// Kernel 1: V'[o][dk] = half(values[o][dk] + grid[dk&15]*skip_w[o][dk>>4])
// ---------------------------------------------------------------------------
__global__ void k_build_v(const float* __restrict__ vals,
                          const float* __restrict__ sw) {
    int id = blockIdx.x * 256 + threadIdx.x;     // o*4096 + dk
    int o  = id >> 12;
    int dk = id & 4095;
    float v = vals[id] + c_grid[dk & 15] * sw[o * DD + (dk >> 4)];
    g_V[id] = __float2half_rn(v);
}

// ---------------------------------------------------------------------------
// Kernel 2: Phi[b][16d+i] = (i==l)?1-w : (i==l+1)?w : 0   (dense write)
// ---------------------------------------------------------------------------
__global__ void k_build_phi(const float* __restrict__ x) {
    int b = blockIdx.x;
    int d = threadIdx.x;
    int l; float w;
    bucketize(x[b * DD + d], l, w);

    __half hv[16];
#pragma unroll
    for (int i = 0; i < 16; ++i) {
        float f = (i == l) ? (1.0f - w) : ((i == l + 1) ? w : 0.0f);
        hv[i] = __float2half_rn(f);
    }
    __half* dst = g_Phi + b * DKN + d * 16;
    *(uint4*)(dst)     = *(const uint4*)&hv[0];
    *(uint4*)(dst + 8) = *(const uint4*)&hv[8];
}

// ---------------------------------------------------------------------------
// Kernel 3: HMMA GEMM  y[2048,256] = Phi @ V'^T + bias
// CTA 64x64, 4 warps (2x2, warp tile 32x32), 3-stage cp.async pipeline.
// Smem rows are 128B; SW128 xor swizzle -> conflict-free cp.async + ldmatrix.
// ---------------------------------------------------------------------------
#define LDMX4(r0, r1, r2, r3, addr)                                       \
    asm volatile("ldmatrix.sync.aligned.m8n8.x4.shared.b16 "              \
                 "{%0,%1,%2,%3}, [%4];"                                   \
                 : "=r"(r0), "=r"(r1), "=r"(r2), "=r"(r3) : "r"(addr))

#define MMA16816(c, a0, a1, a2, a3, b0, b1)                               \
    asm volatile("mma.sync.aligned.m16n8k16.row.col.f32.f16.f16.f32 "     \
                 "{%0,%1,%2,%3}, {%4,%5,%6,%7}, {%8,%9}, {%0,%1,%2,%3};"  \
                 : "+f"(c[0]), "+f"(c[1]), "+f"(c[2]), "+f"(c[3])         \
                 : "r"(a0), "r"(a1), "r"(a2), "r"(a3), "r"(b0), "r"(b1))

__device__ __forceinline__ void load_stage(uint32_t sb, const char* gA,
                                           const char* gB, int kt, int slot,
                                           int tid) {
    uint32_t dstA = sb + slot * STG_BYTES;
    uint32_t dstB = dstA + ASTG;
    const char* srcA = gA + kt * 128;   // 128B col slice of 8192B rows
    const char* srcB = gB + kt * 128;
#pragma unroll
    for (int i = 0; i < 4; ++i) {
        int idx = i * 128 + tid;        // 512 16B-units per operand
        int row = idx >> 3;
        int cb  = idx & 7;
        uint32_t swz = row * 128 + ((cb ^ (row & 7)) << 4);
        asm volatile("cp.async.cg.shared.global [%0], [%1], 16;"
                     :: "r"(dstA + swz), "l"(srcA + row * 8192 + cb * 16)
                     : "memory");
        asm volatile("cp.async.cg.shared.global [%0], [%1], 16;"
                     :: "r"(dstB + swz), "l"(srcB + row * 8192 + cb * 16)
                     : "memory");
    }
}

__global__ __launch_bounds__(128) void k_gemm(const float* __restrict__ skip_b,
                                              float* __restrict__ y) {
    extern __shared__ char smem[];
    uint32_t sb;
    asm("{ .reg .u64 t; cvta.to.shared.u64 t, %1; cvt.u32.u64 %0, t; }"
        : "=r"(sb) : "l"(smem));

    const int tid  = threadIdx.x;
    const int wid  = tid >> 5;
    const int lane = tid & 31;
    const int wm   = (wid & 1) * 32;    // warp M offset in CTA tile
    const int wn   = (wid >> 1) * 32;   // warp N offset
    const int mt   = blockIdx.x >> 2;
    const int nt   = blockIdx.x & 3;
    const char* gA = (const char*)g_Phi + (size_t)mt * MT * 8192;
    const char* gB = (const char*)g_V   + (size_t)nt * NT * 8192;

    // ldmatrix lane addressing: row-in-tile + 16B-unit column offset
    const int lrow = lane & 15;
    const int lcb  = lane >> 4;         // 0 or 1 (adds 8 halfs)

    // Prologue: stages 0, 1
    load_stage(sb, gA, gB, 0, 0, tid);
    asm volatile("cp.async.commit_group;" ::: "memory");
    load_stage(sb, gA, gB, 1, 1, tid);
    asm volatile("cp.async.commit_group;" ::: "memory");

    float acc[2][4][4];
#pragma unroll
    for (int mi = 0; mi < 2; ++mi)
#pragma unroll
        for (int ni = 0; ni < 4; ++ni)
#pragma unroll
            for (int j = 0; j < 4; ++j) acc[mi][ni][j] = 0.f;

    // A lane row bases (swizzle-ready): two 16-row tiles
    const int arow0 = wm + lrow, arow1 = wm + 16 + lrow;
    const int brow0 = wn + lrow, brow1 = wn + 16 + lrow;

#pragma unroll 1
    for (int kt = 0; kt < NKCH; ++kt) {
        asm volatile("cp.async.wait_group 1;" ::: "memory");
        __syncthreads();

        if (kt + 2 < NKCH)
            load_stage(sb, gA, gB, kt + 2, (kt + 2) % STAGES, tid);
        asm volatile("cp.async.commit_group;" ::: "memory");

        uint32_t sA = sb + (kt % STAGES) * STG_BYTES;
        uint32_t sB = sA + ASTG;

#pragma unroll
        for (int k16 = 0; k16 < 4; ++k16) {
            int cu = k16 * 2 + lcb;     // 16B-unit column
            uint32_t a0, a1, a2, a3, a4, a5, a6, a7;
            uint32_t b0, b1, b2, b3, b4, b5, b6, b7;
            LDMX4(a0, a1, a2, a3, sA + arow0 * 128 + ((cu ^ (arow0 & 7)) << 4));
            LDMX4(a4, a5, a6, a7, sA + arow1 * 128 + ((cu ^ (arow1 & 7)) << 4));
            LDMX4(b0, b1, b2, b3, sB + brow0 * 128 + ((cu ^ (brow0 & 7)) << 4));
            LDMX4(b4, b5, b6, b7, sB + brow1 * 128 + ((cu ^ (brow1 & 7)) << 4));

            MMA16816(acc[0][0], a0, a1, a2, a3, b0, b2);
            MMA16816(acc[0][1], a0, a1, a2, a3, b1, b3);
            MMA16816(acc[0][2], a0, a1, a2, a3, b4, b6);
            MMA16816(acc[0][3], a0, a1, a2, a3, b5, b7);
            MMA16816(acc[1][0], a4, a5, a6, a7, b0, b2);
            MMA16816(acc[1][1], a4, a5, a6, a7, b1, b3);
            MMA16816(acc[1][2], a4, a5, a6, a7, b4, b6);
            MMA16816(acc[1][3], a4, a5, a6, a7, b5, b7);
        }
    }

    // Epilogue: add bias, store. d-regs: {m=lane/4, n=(lane%4)*2,+1} and m+8.
    const int m0 = mt * MT + wm + (lane >> 2);
    const int nb = nt * NT + wn + (lane & 3) * 2;
#pragma unroll
    for (int mi = 0; mi < 2; ++mi) {
#pragma unroll
        for (int ni = 0; ni < 4; ++ni) {
            int n = nb + ni * 8;
            float2 bias = *(const float2*)(skip_b + n);
            int m = m0 + mi * 16;
            float2 r0 = make_float2(acc[mi][ni][0] + bias.x,
                                    acc[mi][ni][1] + bias.y);
            float2 r1 = make_float2(acc[mi][ni][2] + bias.x,
                                    acc[mi][ni][3] + bias.y);
            *(float2*)(y + m * OUTN + n)       = r0;
            *(float2*)(y + (m + 8) * OUTN + n) = r1;
        }
    }
}

// ---------------------------------------------------------------------------
extern "C" void kernel_launch(void* const* d_in, const int* in_sizes, int n_in,
                              void* d_out, int out_size) {
    const float* x      = (const float*)d_in[0];  // (B, D)
    const float* values = (const float*)d_in[1];  // (OUT, D, K)
    const float* skip_w = (const float*)d_in[2];  // (OUT, D)
    const float* skip_b = (const float*)d_in[3];  // (OUT,)
    float* y = (float*)d_out;                     // (B, OUT)

    cudaFuncSetAttribute(k_gemm, cudaFuncAttributeMaxDynamicSharedMemorySize,
                         SMEM_BYTES);

    k_build_v<<<(OUTN * DKN) / 256, 256>>>(values, skip_w);
    k_build_phi<<<BB, DD>>>(x);
    k_gemm<<<(BB / MT) * (OUTN / NT), 128, SMEM_BYTES>>>(skip_b, y);
}